// round 1
// baseline (speedup 1.0000x reference)
#include <cuda_runtime.h>

// Problem constants
#define NBATCH   4096
#define TT       256
#define NSTEPS   255   // T-1
#define ND       16
#define SD       8
#define HH       64
#define INX      24    // SD + ND
#define KIN      88    // INX + HH
#define G4       256   // 4*HH
#define NB       32    // batch rows per CTA
#define NTHREADS 256

struct Smem {
    float wz[KIN][G4];     // combined [x,n,h] -> 4H weights (Wx rows 0..23, Wh rows 24..87)
    float bz[G4];
    float w1[2][HH][HH];   // path 0 = mu, path 1 = var
    float w2[2][HH][HH];
    float w3[2][HH][SD];
    float b1[2][HH];
    float b2[2][HH];
    float b3[2][SD];
    float inbuf[NB][KIN];  // per-batch LSTM input: [x(8) | noise(16) | h(64)]
    float a1[2][NB][HH + 1];
    float a2[2][NB][HH + 1];
    float muv[2][NB][SD];
};

__device__ __forceinline__ float sigm(float x) {
    return __fdividef(1.f, 1.f + __expf(-x));
}

__device__ __forceinline__ float ftanh(float x) {
    // tanh(x) = sign(x) * (1 - 2/(e^{2|x|}+1)); safe at large |x| (exp -> inf -> 1)
    float a = fabsf(x);
    float e = __expf(2.f * a);
    float r = 1.f - __fdividef(2.f, e + 1.f);
    return copysignf(r, x);
}

__global__ __launch_bounds__(NTHREADS, 1)
void genlstm_kernel(
    const float* __restrict__ g_noise, const float* __restrict__ g_eps,
    const float* __restrict__ Wx, const float* __restrict__ Wh, const float* __restrict__ b_g,
    const float* __restrict__ Wm1, const float* __restrict__ bm1,
    const float* __restrict__ Wm2, const float* __restrict__ bm2,
    const float* __restrict__ Wm3, const float* __restrict__ bm3,
    const float* __restrict__ Wv1, const float* __restrict__ bv1,
    const float* __restrict__ Wv2, const float* __restrict__ bv2,
    const float* __restrict__ Wv3, const float* __restrict__ bv3,
    float* __restrict__ g_out)
{
    extern __shared__ float smraw[];
    Smem* sm = reinterpret_cast<Smem*>(smraw);
    const int tid = threadIdx.x;
    const int b0  = blockIdx.x * NB;

    // ---- load all weights into SMEM (one time) ----
    for (int i = tid; i < INX * G4; i += NTHREADS) sm->wz[i >> 8][i & 255] = Wx[i];
    for (int i = tid; i < HH * G4;  i += NTHREADS) sm->wz[INX + (i >> 8)][i & 255] = Wh[i];
    for (int i = tid; i < G4; i += NTHREADS) sm->bz[i] = b_g[i];
    for (int i = tid; i < HH * HH; i += NTHREADS) {
        int r = i >> 6, c = i & 63;
        sm->w1[0][r][c] = Wm1[i]; sm->w1[1][r][c] = Wv1[i];
        sm->w2[0][r][c] = Wm2[i]; sm->w2[1][r][c] = Wv2[i];
    }
    for (int i = tid; i < HH * SD; i += NTHREADS) {
        int r = i >> 3, c = i & 7;
        sm->w3[0][r][c] = Wm3[i]; sm->w3[1][r][c] = Wv3[i];
    }
    if (tid < HH) {
        sm->b1[0][tid] = bm1[tid]; sm->b1[1][tid] = bv1[tid];
        sm->b2[0][tid] = bm2[tid]; sm->b2[1][tid] = bv2[tid];
    }
    if (tid < SD) { sm->b3[0][tid] = bm3[tid]; sm->b3[1][tid] = bv3[tid]; }
    for (int i = tid; i < NB * KIN; i += NTHREADS) sm->inbuf[i / KIN][i % KIN] = 0.f;
    __syncthreads();

    // ---- thread roles ----
    const int uA  = tid & 63;            // LSTM: hidden unit
    const int nA0 = (tid >> 6) * 8;      // LSTM: 8 batch rows
    const int oB  = tid & 63;            // MLP L1/L2: output unit
    const int pB  = (tid >> 6) & 1;      // MLP path (0=mu, 1=var)
    const int nB0 = (tid >> 7) * 16;     // MLP: 16 batch rows
    const int dD  = tid & 7;             // L3 output dim
    const int pD  = (tid >> 3) & 1;
    const int nD0 = (tid >> 4) * 2;      // L3: 2 batch rows
    const int nE  = tid >> 3;            // elementwise: batch row
    const int dE  = tid & 7;             // elementwise: series dim

    // out[:,0,:] = 0 and preload noise for step 0
    {
        g_out[((size_t)(b0 + nE) * TT) * SD + dE] = 0.f;
        const float* np = g_noise + ((size_t)(b0 + nE) * NSTEPS) * ND;
        sm->inbuf[nE][SD + 2 * dE]     = np[2 * dE];
        sm->inbuf[nE][SD + 2 * dE + 1] = np[2 * dE + 1];
    }

    float c[8];
#pragma unroll
    for (int j = 0; j < 8; j++) c[j] = 0.f;
    float cum = 0.f;

    for (int s = 0; s < NSTEPS; s++) {
        __syncthreads();   // inbuf (x, noise, h) ready

        // ---- Phase A: z = [x,n,h] @ W + b, four gates per thread ----
        float ai[8], af[8], ag[8], ao[8];
        {
            float bi = sm->bz[uA],       bf = sm->bz[uA + 64],
                  bg = sm->bz[uA + 128], bo = sm->bz[uA + 192];
#pragma unroll
            for (int j = 0; j < 8; j++) { ai[j] = bi; af[j] = bf; ag[j] = bg; ao[j] = bo; }
        }
#pragma unroll 4
        for (int k = 0; k < KIN; k++) {
            float w0 = sm->wz[k][uA];
            float w1 = sm->wz[k][uA + 64];
            float w2 = sm->wz[k][uA + 128];
            float w3 = sm->wz[k][uA + 192];
#pragma unroll
            for (int j = 0; j < 8; j++) {
                float x = sm->inbuf[nA0 + j][k];
                ai[j] = fmaf(w0, x, ai[j]);
                af[j] = fmaf(w1, x, af[j]);
                ag[j] = fmaf(w2, x, ag[j]);
                ao[j] = fmaf(w3, x, ao[j]);
            }
        }
        __syncthreads();   // all inbuf reads complete before h overwrite

        // ---- LSTM elementwise: c in registers, h -> smem ----
#pragma unroll
        for (int j = 0; j < 8; j++) {
            float ii = sigm(ai[j]);
            float ff = sigm(af[j]);
            float gg = ftanh(ag[j]);
            float oo = sigm(ao[j]);
            c[j] = ff * c[j] + ii * gg;
            float h = oo * ftanh(c[j]);
            sm->inbuf[nA0 + j][INX + uA] = h;
        }
        __syncthreads();

        // ---- Phase B: MLP layer 1 (both paths) ----
        {
            float acc[16];
            float bb = sm->b1[pB][oB];
#pragma unroll
            for (int j = 0; j < 16; j++) acc[j] = bb;
#pragma unroll 4
            for (int k = 0; k < HH; k++) {
                float w = sm->w1[pB][k][oB];
#pragma unroll
                for (int j = 0; j < 16; j++)
                    acc[j] = fmaf(w, sm->inbuf[nB0 + j][INX + k], acc[j]);
            }
#pragma unroll
            for (int j = 0; j < 16; j++)
                sm->a1[pB][nB0 + j][oB] = fmaxf(acc[j], 0.f);
        }
        __syncthreads();

        // ---- Phase C: MLP layer 2 ----
        {
            float acc[16];
            float bb = sm->b2[pB][oB];
#pragma unroll
            for (int j = 0; j < 16; j++) acc[j] = bb;
#pragma unroll 4
            for (int k = 0; k < HH; k++) {
                float w = sm->w2[pB][k][oB];
#pragma unroll
                for (int j = 0; j < 16; j++)
                    acc[j] = fmaf(w, sm->a1[pB][nB0 + j][k], acc[j]);
            }
#pragma unroll
            for (int j = 0; j < 16; j++)
                sm->a2[pB][nB0 + j][oB] = fmaxf(acc[j], 0.f);
        }
        __syncthreads();

        // ---- Phase D: MLP layer 3 -> mu / logvar ----
        {
            float acc0 = sm->b3[pD][dD];
            float acc1 = acc0;
#pragma unroll 4
            for (int k = 0; k < HH; k++) {
                float w = sm->w3[pD][k][dD];
                acc0 = fmaf(w, sm->a2[pD][nD0][k], acc0);
                acc1 = fmaf(w, sm->a2[pD][nD0 + 1][k], acc1);
            }
            sm->muv[pD][nD0][dD]     = acc0;
            sm->muv[pD][nD0 + 1][dD] = acc1;
        }
        __syncthreads();

        // ---- Phase E: sample, cumsum, store, stage next inputs ----
        {
            float mu = sm->muv[0][nE][dE];
            float vv = sm->muv[1][nE][dE];
            float e  = g_eps[((size_t)(b0 + nE) * NSTEPS + s) * SD + dE];
            float x  = fmaf(__expf(0.5f * vv), e, mu);
            cum += x;
            g_out[((size_t)(b0 + nE) * TT + (s + 1)) * SD + dE] = cum;
            sm->inbuf[nE][dE] = x;
            if (s + 1 < NSTEPS) {
                const float* np = g_noise + ((size_t)(b0 + nE) * NSTEPS + (s + 1)) * ND;
                sm->inbuf[nE][SD + 2 * dE]     = np[2 * dE];
                sm->inbuf[nE][SD + 2 * dE + 1] = np[2 * dE + 1];
            }
        }
        // loop-top __syncthreads guards these writes
    }
}

extern "C" void kernel_launch(void* const* d_in, const int* in_sizes, int n_in,
                              void* d_out, int out_size) {
    const float* noise = (const float*)d_in[0];
    const float* eps   = (const float*)d_in[1];
    const float* Wx    = (const float*)d_in[2];
    const float* Wh    = (const float*)d_in[3];
    const float* b     = (const float*)d_in[4];
    const float* Wm1   = (const float*)d_in[5];
    const float* bm1   = (const float*)d_in[6];
    const float* Wm2   = (const float*)d_in[7];
    const float* bm2   = (const float*)d_in[8];
    const float* Wm3   = (const float*)d_in[9];
    const float* bm3   = (const float*)d_in[10];
    const float* Wv1   = (const float*)d_in[11];
    const float* bv1   = (const float*)d_in[12];
    const float* Wv2   = (const float*)d_in[13];
    const float* bv2   = (const float*)d_in[14];
    const float* Wv3   = (const float*)d_in[15];
    const float* bv3   = (const float*)d_in[16];
    float* out = (float*)d_out;

    const int smem_bytes = (int)sizeof(Smem);
    cudaFuncSetAttribute(genlstm_kernel,
                         cudaFuncAttributeMaxDynamicSharedMemorySize, smem_bytes);

    genlstm_kernel<<<NBATCH / NB, NTHREADS, smem_bytes>>>(
        noise, eps, Wx, Wh, b,
        Wm1, bm1, Wm2, bm2, Wm3, bm3,
        Wv1, bv1, Wv2, bv2, Wv3, bv3,
        out);
}

// round 2
// speedup vs baseline: 1.0940x; 1.0940x over previous
#include <cuda_runtime.h>

// Problem constants
#define NBATCH   4096
#define TT       256
#define NSTEPS   255   // T-1
#define ND       16
#define SD       8
#define HH       64
#define INX      24    // SD + ND
#define KIN      88    // INX + HH
#define G4       256   // 4*HH
#define NB       32    // batch rows per CTA
#define NBP      34    // padded batch stride (even -> 8B-aligned float2, bank-spread)
#define NTHREADS 512

typedef unsigned long long u64;

struct Smem {
    float wzi[KIN][G4];     // gate-interleaved LSTM weights: [k][u*4 + gate]
    float bz[G4];           // bias, original order gate*64+u
    float w1[2][HH][HH];    // path 0 = mu, 1 = var
    float w2[2][HH][HH];
    float w3s[HH][2][SD];   // [k][path][d] (bank-spread for Phase D)
    float b1[2][HH];
    float b2[2][HH];
    float b3[2][SD];
    float inT[KIN][NBP];    // k-major LSTM input: rows 0..7 = x, 8..23 = noise, 24..87 = h
    float a1T[2][HH][NBP];  // k-major activations
    float a2T[2][HH][NBP];
    float muv[2][NB][SD];
};

// ---- packed f32x2 helpers (Blackwell FFMA2 path) ----
__device__ __forceinline__ u64 pk2(float a, float b) {
    u64 r; asm("mov.b64 %0, {%1, %2};" : "=l"(r) : "f"(a), "f"(b)); return r;
}
__device__ __forceinline__ void upk2(u64 v, float& a, float& b) {
    asm("mov.b64 {%0, %1}, %2;" : "=f"(a), "=f"(b) : "l"(v));
}
__device__ __forceinline__ u64 fma2(u64 a, u64 b, u64 c) {
    u64 d; asm("fma.rn.f32x2 %0, %1, %2, %3;" : "=l"(d) : "l"(a), "l"(b), "l"(c)); return d;
}

__device__ __forceinline__ float sigm(float x) {
    return __fdividef(1.f, 1.f + __expf(-x));
}
__device__ __forceinline__ float ftanh(float x) {
    float a = fabsf(x);
    float e = __expf(2.f * a);
    float r = 1.f - __fdividef(2.f, e + 1.f);
    return copysignf(r, x);
}

__global__ __launch_bounds__(NTHREADS, 1)
void genlstm_kernel(
    const float* __restrict__ g_noise, const float* __restrict__ g_eps,
    const float* __restrict__ Wx, const float* __restrict__ Wh, const float* __restrict__ b_g,
    const float* __restrict__ Wm1, const float* __restrict__ bm1,
    const float* __restrict__ Wm2, const float* __restrict__ bm2,
    const float* __restrict__ Wm3, const float* __restrict__ bm3,
    const float* __restrict__ Wv1, const float* __restrict__ bv1,
    const float* __restrict__ Wv2, const float* __restrict__ bv2,
    const float* __restrict__ Wv3, const float* __restrict__ bv3,
    float* __restrict__ g_out)
{
    extern __shared__ float smraw[];
    Smem* sm = reinterpret_cast<Smem*>(smraw);
    const int tid = threadIdx.x;
    const int b0  = blockIdx.x * NB;

    // ---- one-time weight staging ----
    for (int i = tid; i < KIN * G4; i += NTHREADS) {
        int k = i >> 8, col = i & 255, g = col >> 6, u = col & 63;
        float v = (k < INX) ? Wx[i] : Wh[(k - INX) * G4 + col];
        sm->wzi[k][u * 4 + g] = v;
    }
    for (int i = tid; i < G4; i += NTHREADS) sm->bz[i] = b_g[i];
    for (int i = tid; i < HH * HH; i += NTHREADS) {
        int r = i >> 6, c = i & 63;
        sm->w1[0][r][c] = Wm1[i]; sm->w1[1][r][c] = Wv1[i];
        sm->w2[0][r][c] = Wm2[i]; sm->w2[1][r][c] = Wv2[i];
    }
    for (int i = tid; i < HH * SD; i += NTHREADS) {
        int r = i >> 3, c = i & 7;
        sm->w3s[r][0][c] = Wm3[i]; sm->w3s[r][1][c] = Wv3[i];
    }
    if (tid < HH) {
        sm->b1[0][tid] = bm1[tid]; sm->b1[1][tid] = bv1[tid];
        sm->b2[0][tid] = bm2[tid]; sm->b2[1][tid] = bv2[tid];
    }
    if (tid < SD) { sm->b3[0][tid] = bm3[tid]; sm->b3[1][tid] = bv3[tid]; }
    for (int i = tid; i < KIN * NBP; i += NTHREADS) sm->inT[i / NBP][i % NBP] = 0.f;

    // ---- thread roles ----
    const int uA  = tid & 63;            // LSTM: hidden unit
    const int jA0 = (tid >> 6) * 4;      // LSTM: 4 batch rows (2 packed pairs)
    const int oB  = tid & 63;            // MLP L1/L2: output unit
    const int pB  = (tid >> 6) & 1;      // MLP path
    const int jB0 = (tid >> 7) * 8;      // MLP: 8 batch rows (4 pairs)
    const int dD  = tid & 7;             // L3: output dim
    const int pD  = (tid >> 3) & 1;
    const int nD  = tid >> 4;            // L3: batch row (0..31)
    const int nE  = (tid >> 3) & 31;     // elementwise: batch row (tid < 256 only)
    const int dE  = tid & 7;

    // initial output row (t = 0) and noise(step 0)
    if (tid < 256) {
        g_out[((size_t)(b0 + nE) * TT) * SD + dE] = 0.f;
        const float2 nz = *(const float2*)&g_noise[((size_t)(b0 + nE) * NSTEPS) * ND + 2 * dE];
        sm->inT[SD + 2 * dE][nE]     = nz.x;
        sm->inT[SD + 2 * dE + 1][nE] = nz.y;
    }

    float c[4];
#pragma unroll
    for (int j = 0; j < 4; j++) c[j] = 0.f;
    float cum = 0.f;

    for (int s = 0; s < NSTEPS; s++) {
        // prefetch next-step global inputs into registers (consumed in Phase E)
        float epsv = 0.f; float2 nz = make_float2(0.f, 0.f);
        if (tid < 256) {
            epsv = g_eps[((size_t)(b0 + nE) * NSTEPS + s) * SD + dE];
            if (s + 1 < NSTEPS)
                nz = *(const float2*)&g_noise[((size_t)(b0 + nE) * NSTEPS + (s + 1)) * ND + 2 * dE];
        }

        __syncthreads();   // inT (x, noise, h) ready

        // ---- Phase A: z = [x,n,h] @ W + b (4 gates x 2 batch-pairs, FFMA2) ----
        u64 acc[4][2];
        {
            float bi = sm->bz[uA],       bf = sm->bz[uA + 64],
                  bg = sm->bz[uA + 128], bo = sm->bz[uA + 192];
            acc[0][0] = acc[0][1] = pk2(bi, bi);
            acc[1][0] = acc[1][1] = pk2(bf, bf);
            acc[2][0] = acc[2][1] = pk2(bg, bg);
            acc[3][0] = acc[3][1] = pk2(bo, bo);
        }
#pragma unroll 4
        for (int k = 0; k < KIN; k++) {
            float4 w4 = *(const float4*)&sm->wzi[k][uA * 4];
            u64 x0 = *(const u64*)&sm->inT[k][jA0];
            u64 x1 = *(const u64*)&sm->inT[k][jA0 + 2];
            u64 w0 = pk2(w4.x, w4.x), w1_ = pk2(w4.y, w4.y);
            u64 w2_ = pk2(w4.z, w4.z), w3_ = pk2(w4.w, w4.w);
            acc[0][0] = fma2(w0, x0, acc[0][0]);  acc[0][1] = fma2(w0, x1, acc[0][1]);
            acc[1][0] = fma2(w1_, x0, acc[1][0]); acc[1][1] = fma2(w1_, x1, acc[1][1]);
            acc[2][0] = fma2(w2_, x0, acc[2][0]); acc[2][1] = fma2(w2_, x1, acc[2][1]);
            acc[3][0] = fma2(w3_, x0, acc[3][0]); acc[3][1] = fma2(w3_, x1, acc[3][1]);
        }
        __syncthreads();   // all inT reads done before h overwrite

        // ---- LSTM elementwise: c in regs, h -> inT (packed stores) ----
#pragma unroll
        for (int p = 0; p < 2; p++) {
            float i0, i1, f0, f1, g0, g1, o0, o1;
            upk2(acc[0][p], i0, i1); upk2(acc[1][p], f0, f1);
            upk2(acc[2][p], g0, g1); upk2(acc[3][p], o0, o1);
            float c0 = sigm(f0) * c[2 * p]     + sigm(i0) * ftanh(g0);
            float c1 = sigm(f1) * c[2 * p + 1] + sigm(i1) * ftanh(g1);
            c[2 * p] = c0; c[2 * p + 1] = c1;
            float h0 = sigm(o0) * ftanh(c0);
            float h1 = sigm(o1) * ftanh(c1);
            *(u64*)&sm->inT[INX + uA][jA0 + 2 * p] = pk2(h0, h1);
        }
        __syncthreads();

        // ---- Phase B: MLP layer 1 (both paths, FFMA2) ----
        {
            u64 acc1[4];
            float bb = sm->b1[pB][oB];
#pragma unroll
            for (int p = 0; p < 4; p++) acc1[p] = pk2(bb, bb);
#pragma unroll 4
            for (int k = 0; k < HH; k++) {
                float w = sm->w1[pB][k][oB];
                u64 ww = pk2(w, w);
#pragma unroll
                for (int p = 0; p < 4; p++) {
                    u64 x = *(const u64*)&sm->inT[INX + k][jB0 + 2 * p];
                    acc1[p] = fma2(ww, x, acc1[p]);
                }
            }
#pragma unroll
            for (int p = 0; p < 4; p++) {
                float v0, v1; upk2(acc1[p], v0, v1);
                *(u64*)&sm->a1T[pB][oB][jB0 + 2 * p] = pk2(fmaxf(v0, 0.f), fmaxf(v1, 0.f));
            }
        }
        __syncthreads();

        // ---- Phase C: MLP layer 2 ----
        {
            u64 acc2[4];
            float bb = sm->b2[pB][oB];
#pragma unroll
            for (int p = 0; p < 4; p++) acc2[p] = pk2(bb, bb);
#pragma unroll 4
            for (int k = 0; k < HH; k++) {
                float w = sm->w2[pB][k][oB];
                u64 ww = pk2(w, w);
#pragma unroll
                for (int p = 0; p < 4; p++) {
                    u64 x = *(const u64*)&sm->a1T[pB][k][jB0 + 2 * p];
                    acc2[p] = fma2(ww, x, acc2[p]);
                }
            }
#pragma unroll
            for (int p = 0; p < 4; p++) {
                float v0, v1; upk2(acc2[p], v0, v1);
                *(u64*)&sm->a2T[pB][oB][jB0 + 2 * p] = pk2(fmaxf(v0, 0.f), fmaxf(v1, 0.f));
            }
        }
        __syncthreads();

        // ---- Phase D: MLP layer 3 -> mu / logvar (scalar, one output/thread) ----
        {
            float acc3 = sm->b3[pD][dD];
#pragma unroll 8
            for (int k = 0; k < HH; k++)
                acc3 = fmaf(sm->w3s[k][pD][dD], sm->a2T[pD][k][nD], acc3);
            sm->muv[pD][nD][dD] = acc3;
        }
        __syncthreads();

        // ---- Phase E: sample, cumsum, store, stage next inputs ----
        if (tid < 256) {
            float mu = sm->muv[0][nE][dE];
            float vv = sm->muv[1][nE][dE];
            float x  = fmaf(__expf(0.5f * vv), epsv, mu);
            cum += x;
            g_out[((size_t)(b0 + nE) * TT + (s + 1)) * SD + dE] = cum;
            sm->inT[dE][nE] = x;
            if (s + 1 < NSTEPS) {
                sm->inT[SD + 2 * dE][nE]     = nz.x;
                sm->inT[SD + 2 * dE + 1][nE] = nz.y;
            }
        }
        // loop-top __syncthreads guards these writes
    }
}

extern "C" void kernel_launch(void* const* d_in, const int* in_sizes, int n_in,
                              void* d_out, int out_size) {
    const float* noise = (const float*)d_in[0];
    const float* eps   = (const float*)d_in[1];
    const float* Wx    = (const float*)d_in[2];
    const float* Wh    = (const float*)d_in[3];
    const float* b     = (const float*)d_in[4];
    const float* Wm1   = (const float*)d_in[5];
    const float* bm1   = (const float*)d_in[6];
    const float* Wm2   = (const float*)d_in[7];
    const float* bm2   = (const float*)d_in[8];
    const float* Wm3   = (const float*)d_in[9];
    const float* bm3   = (const float*)d_in[10];
    const float* Wv1   = (const float*)d_in[11];
    const float* bv1   = (const float*)d_in[12];
    const float* Wv2   = (const float*)d_in[13];
    const float* bv2   = (const float*)d_in[14];
    const float* Wv3   = (const float*)d_in[15];
    const float* bv3   = (const float*)d_in[16];
    float* out = (float*)d_out;

    const int smem_bytes = (int)sizeof(Smem);
    cudaFuncSetAttribute(genlstm_kernel,
                         cudaFuncAttributeMaxDynamicSharedMemorySize, smem_bytes);

    genlstm_kernel<<<NBATCH / NB, NTHREADS, smem_bytes>>>(
        noise, eps, Wx, Wh, b,
        Wm1, bm1, Wm2, bm2, Wm3, bm3,
        Wv1, bv1, Wv2, bv2, Wv3, bv3,
        out);
}